// round 8
// baseline (speedup 1.0000x reference)
#include <cuda_runtime.h>
#include <math.h>
#include <math_constants.h>

#define BS 16
#define Q 900
#define NC 92
#define T 100
#define NT (BS * T)   // 1600

#define QW 3          // q per warp in cost kernel
#define CW 12         // warps per cost block
#define QPB (QW * CW) // 36 q per block; Q/QPB = 25 blocks per batch

#define LTH 128       // lsa threads
#define LNK 8         // cols per thread in lsa
#define QP 1024       // padded row stride (128*8)

// Transposed per-batch cost slice, padded: ct[b][t][0..899]=cost, [900..1023]=+INF
__device__ float g_ct[BS][T][QP];

// ---------------------------------------------------------------------------
// Kernel 1: cost matrix. 12 warps/block, THREE q per warp, targets staged in
// smem once per block; target-derived math amortized across the 3 q.
// ---------------------------------------------------------------------------
__global__ void __launch_bounds__(32 * CW) cost_kernel(
    const float* __restrict__ logits,   // [BS*Q, NC]
    const float* __restrict__ pboxes,   // [BS*Q, 4]  cxcywh
    const int*   __restrict__ tgt_ids,  // [NT]
    const float* __restrict__ tbox,     // [NT, 4]    xyxy
    float* __restrict__ C)              // [BS*Q, NT]
{
    const int b     = blockIdx.x / (Q / QPB);
    const int qbase = (blockIdx.x % (Q / QPB)) * QPB;
    const int tid   = threadIdx.x;
    const int lane  = tid & 31;
    const int w     = tid >> 5;          // 0..11
    const int q0    = qbase + QW * w;
    const int bq0   = b * Q + q0;

    __shared__ float4 s_xy[NT];          // target xyxy
    __shared__ int    s_id[NT];          // target class ids
    __shared__ float  sp[QPB][NC];       // per-q softmax probs

    // stage targets once per block
    const float4* tb4 = reinterpret_cast<const float4*>(tbox);
    for (int j = tid; j < NT; j += 32 * CW) {
        s_xy[j] = __ldg(tb4 + j);
        s_id[j] = __ldg(tgt_ids + j);
    }

    // per-warp softmax for each of the 3 q
    #pragma unroll
    for (int s = 0; s < QW; ++s) {
        const float* L = logits + (size_t)(bq0 + s) * NC;
        float l0 = (lane      < NC) ? __ldg(L + lane)      : -CUDART_INF_F;
        float l1 = (lane + 32 < NC) ? __ldg(L + lane + 32) : -CUDART_INF_F;
        float l2 = (lane + 64 < NC) ? __ldg(L + lane + 64) : -CUDART_INF_F;

        float m = fmaxf(l0, fmaxf(l1, l2));
        #pragma unroll
        for (int o = 16; o; o >>= 1) m = fmaxf(m, __shfl_xor_sync(0xffffffffu, m, o));

        float e0 = (lane      < NC) ? expf(l0 - m) : 0.f;
        float e1 = (lane + 32 < NC) ? expf(l1 - m) : 0.f;
        float e2 = (lane + 64 < NC) ? expf(l2 - m) : 0.f;
        float sm = e0 + e1 + e2;
        #pragma unroll
        for (int o = 16; o; o >>= 1) sm += __shfl_xor_sync(0xffffffffu, sm, o);
        const float inv_s = 1.0f / sm;

        if (lane      < NC) sp[QW * w + s][lane]      = e0 * inv_s;
        if (lane + 32 < NC) sp[QW * w + s][lane + 32] = e1 * inv_s;
        if (lane + 64 < NC) sp[QW * w + s][lane + 64] = e2 * inv_s;
    }
    __syncthreads();

    // per-q constants
    float cxA[QW], cyA[QW], wdA[QW], htA[QW];
    float px0A[QW], py0A[QW], px1A[QW], py1A[QW], areaA[QW];
    #pragma unroll
    for (int s = 0; s < QW; ++s) {
        const int bq = bq0 + s;
        cxA[s] = pboxes[bq * 4 + 0];
        cyA[s] = pboxes[bq * 4 + 1];
        wdA[s] = pboxes[bq * 4 + 2];
        htA[s] = pboxes[bq * 4 + 3];
        px0A[s] = cxA[s] - wdA[s] * 0.5f;  py0A[s] = cyA[s] - htA[s] * 0.5f;
        px1A[s] = cxA[s] + wdA[s] * 0.5f;  py1A[s] = cyA[s] + htA[s] * 0.5f;
        areaA[s] = (px1A[s] - px0A[s]) * (py1A[s] - py0A[s]);
    }

    float* Crow0 = C + (size_t)bq0 * NT;

    for (int j = lane; j < NT; j += 32) {
        const int id = s_id[j];
        const float4 tb = s_xy[j];
        const float tx0 = tb.x, ty0 = tb.y, tx1 = tb.z, ty1 = tb.w;

        // target-derived (shared across 3 q)
        const float tcx = (tx0 + tx1) * 0.5f, tcy = (ty0 + ty1) * 0.5f;
        const float tw  = tx1 - tx0,          th  = ty1 - ty0;
        const float area_b = tw * th;

        #pragma unroll
        for (int s = 0; s < QW; ++s) {
            const float prob = sp[QW * w + s][id];

            const float cb = fabsf(cxA[s] - tcx) + fabsf(cyA[s] - tcy)
                           + fabsf(wdA[s] - tw)  + fabsf(htA[s] - th);

            const float ltx = fmaxf(px0A[s], tx0), lty = fmaxf(py0A[s], ty0);
            const float rbx = fminf(px1A[s], tx1), rby = fminf(py1A[s], ty1);
            const float iw = fmaxf(rbx - ltx, 0.f), ih = fmaxf(rby - lty, 0.f);
            const float inter = iw * ih;
            const float uni = areaA[s] + area_b - inter;
            const float iou = inter / uni;
            const float lcx = fminf(px0A[s], tx0), lcy = fminf(py0A[s], ty0);
            const float rcx = fmaxf(px1A[s], tx1), rcy = fmaxf(py1A[s], ty1);
            const float cw = fmaxf(rcx - lcx, 0.f), ch = fmaxf(rcy - lcy, 0.f);
            const float ac = cw * ch;
            const float giou = iou - (ac - uni) / ac;

            float cost = 5.0f * cb + (-prob);
            cost = cost + 2.0f * (-giou);

            Crow0[(size_t)s * NT + j] = cost;
        }
    }
}

// ---------------------------------------------------------------------------
// Kernel 2: smem-tiled transpose C -> g_ct (own-batch slice) + INF padding.
// ---------------------------------------------------------------------------
__global__ void __launch_bounds__(256) transpose_kernel(const float* __restrict__ C)
{
    const int b  = blockIdx.y;
    const int q0 = blockIdx.x * 32;      // 32 tiles cover q in [0,1024)
    const int tx = threadIdx.x;          // 32
    const int ty = threadIdx.y;          // 8

    __shared__ float tile[32][33];

    #pragma unroll
    for (int t0 = 0; t0 < T; t0 += 32) {
        for (int r = ty; r < 32; r += 8) {
            const int q = q0 + r;
            const int t = t0 + tx;
            float v = 0.f;
            if (q < Q && t < T)
                v = __ldg(C + (size_t)(b * Q + q) * NT + b * T + t);
            tile[r][tx] = v;
        }
        __syncthreads();
        for (int r = ty; r < 32; r += 8) {
            const int t = t0 + r;
            if (t < T) {
                const int q = q0 + tx;
                g_ct[b][t][q] = (q < Q) ? tile[tx][r] : CUDART_INF_F;
            }
        }
        __syncthreads();
    }
}

// ---------------------------------------------------------------------------
// Kernel 3: JV LSA, 128 threads per batch. Mono-u32 keys, REDUX argmin,
// delta-accumulator, asm-predicated sway store (no branches in scan),
// upj[] shadow of u[p[]] (parallel LDS lookup), 1 barrier/iter, prefetch.
// ---------------------------------------------------------------------------
__global__ void __launch_bounds__(LTH) lsa_kernel(
    float* __restrict__ rows_out,   // [BS*T]
    float* __restrict__ cols_out)   // [BS*T]
{
    const int b    = blockIdx.x;
    const int tid  = threadIdx.x;
    const int lane = tid & 31;
    const int wid  = tid >> 5;

    __shared__ float u[T + 1];
    __shared__ int   p[QP + 1];
    __shared__ float upj[QP + 1];   // upj[j] == u[p[j]] (maintained invariant)
    __shared__ int   sway[QP + 1];
    __shared__ int   ans[T];
    __shared__ unsigned long long red[2][4];

    for (int k = tid; k <= T;  k += LTH) u[k] = 0.f;
    for (int k = tid; k <= QP; k += LTH) { p[k] = 0; upj[k] = 0.f; }

    float    v[LNK];
    unsigned minm[LNK];
    float    val[LNK];
    #pragma unroll
    for (int k = 0; k < LNK; ++k) v[k] = 0.f;
    __syncthreads();

    const float* base = &g_ct[b][0][0];
    const unsigned sway_addr0 =
        (unsigned)__cvta_generic_to_shared(&sway[0]) + 4u * (1 + tid);
    int itpar = 0;

    for (int i = 1; i <= T; ++i) {
        #pragma unroll
        for (int k = 0; k < LNK; ++k) minm[k] = 0xFFFFFFFFu;
        unsigned usedmask = 0;
        if (tid == 0) { p[0] = i; upj[0] = u[i]; }

        int   j0   = 0;
        float u_i0 = u[i];
        float D    = 0.f;

        // prefetch root row
        {
            const float* crow = base + (size_t)(i - 1) * QP;
            #pragma unroll
            for (int k = 0; k < LNK; ++k) val[k] = __ldg(crow + tid + LTH * k);
        }

        while (true) {
            // mark j0 used (at most one (thread,k) matches)
            {
                const int d = j0 - 1 - tid;
                if (d >= 0 && (d & (LTH - 1)) == 0) usedmask |= 1u << (d >> 7);
            }

            const float adj = u_i0 - D;
            unsigned wmin = 0xFFFFFFFFu;
            unsigned mk[LNK];
            #pragma unroll
            for (int k = 0; k < LNK; ++k) {
                const float curf = (val[k] - adj) - v[k];
                const unsigned cu = __float_as_uint(curf);
                unsigned cm = (cu & 0x80000000u) ? ~cu : (cu | 0x80000000u);
                const bool isused = (usedmask >> k) & 1u;
                cm = isused ? 0xFFFFFFFFu : cm;
                const unsigned better = (cm < minm[k]) ? 1u : 0u;
                // branch-free conditional store of the predecessor pointer
                asm volatile(
                    "{\n\t.reg .pred pp;\n\t"
                    "setp.ne.u32 pp, %0, 0;\n\t"
                    "@pp st.shared.u32 [%1], %2;\n\t}"
                    :: "r"(better), "r"(sway_addr0 + 4u * LTH * k), "r"(j0));
                minm[k] = better ? cm : minm[k];
                mk[k] = isused ? 0xFFFFFFFFu : minm[k];
                wmin = umin(wmin, mk[k]);
            }
            const unsigned wbest = __reduce_min_sync(0xffffffffu, wmin);

            unsigned idxc = 0x7FFFFFFFu;
            #pragma unroll
            for (int k = 0; k < LNK; ++k) {
                const int jc = 1 + tid + LTH * k;
                if (mk[k] == wbest) idxc = umin(idxc, (unsigned)jc);
            }
            const unsigned widx = __reduce_min_sync(0xffffffffu, idxc);

            if (lane == 0)
                red[itpar][wid] = ((unsigned long long)wbest << 32) | widx;
            __syncthreads();                                   // the ONE barrier

            unsigned long long bk = red[itpar][0];
            #pragma unroll
            for (int ww = 1; ww < 4; ++ww) {
                const unsigned long long c2 = red[itpar][ww];
                if (c2 < bk) bk = c2;
            }
            itpar ^= 1;

            const unsigned bm = (unsigned)(bk >> 32);
            const int      j1 = (int)(unsigned)bk;

            // parallel lookups: j1's row and that row's dual (upj invariant)
            const int   i0n = p[j1];
            const float un  = upj[j1];

            // prefetch next row early (row i0n untouched by this iter's updates)
            if (i0n) {
                const float* nrow = base + (size_t)(i0n - 1) * QP;
                #pragma unroll
                for (int k = 0; k < LNK; ++k) val[k] = __ldg(nrow + tid + LTH * k);
            }

            const unsigned ub = (bm & 0x80000000u) ? (bm ^ 0x80000000u) : ~bm;
            const float delta_raw = __uint_as_float(ub);
            const float delta = delta_raw - D;
            D = delta_raw;

            // sparse dual updates (rows of used columns are distinct -> race-free)
            unsigned mm = usedmask;
            while (mm) {
                const int k = __ffs(mm) - 1; mm &= mm - 1;
                const int jc = 1 + tid + LTH * k;
                u[p[jc]] += delta;
                upj[jc]  += delta;
                v[k]     -= delta;
            }
            if (tid == 0) { u[i] += delta; upj[0] += delta; }   // virtual col 0

            j0 = j1;
            if (!i0n) break;
            u_i0 = un;
        }

        __syncthreads();   // sway/u settled before augment
        if (tid == 0) {
            int j0a = j0;
            while (j0a) {
                const int j1a = sway[j0a];
                p[j0a]   = p[j1a];
                upj[j0a] = upj[j1a];
                j0a = j1a;
            }
        }
        __syncthreads();   // p settled before next phase
    }

    // extract: ans[t] = pred column assigned to target t
    for (int jc = 1 + tid; jc <= Q; jc += LTH) {
        const int r = p[jc];
        if (r > 0) ans[r - 1] = jc - 1;
    }
    __syncthreads();

    // rows = sorted pred indices, cols = targets ordered by their pred index
    if (tid < T) {
        const int a = ans[tid];
        int rank = 0;
        #pragma unroll 4
        for (int tt = 0; tt < T; ++tt) rank += (ans[tt] < a);
        rows_out[b * T + rank] = (float)a;
        cols_out[b * T + rank] = (float)tid;
    }
}

// ---------------------------------------------------------------------------
extern "C" void kernel_launch(void* const* d_in, const int* in_sizes, int n_in,
                              void* d_out, int out_size) {
    const float* logits = (const float*)d_in[0];
    const float* pboxes = (const float*)d_in[1];
    const int*   ids    = (const int*)d_in[2];
    const float* tbox   = (const float*)d_in[3];
    float* out = (float*)d_out;

    const long long CN = (long long)BS * Q * NT;   // 23,040,000

    cost_kernel<<<BS * (Q / QPB), 32 * CW>>>(logits, pboxes, ids, tbox, out);

    dim3 tgrid(32, BS);
    dim3 tblk(32, 8);
    transpose_kernel<<<tgrid, tblk>>>(out);

    if ((long long)out_size >= CN + 2LL * BS * T) {
        lsa_kernel<<<BS, LTH>>>(out + CN, out + CN + (long long)BS * T);
    }
}

// round 9
// speedup vs baseline: 1.4418x; 1.4418x over previous
#include <cuda_runtime.h>
#include <math.h>
#include <math_constants.h>

#define BS 16
#define Q 900
#define NC 92
#define T 100
#define NT (BS * T)   // 1600

#define CQB 12        // q's (=warps) per cost block; Q/CQB = 75
#define LTH 256       // lsa threads
#define LNK 4         // cols per thread in lsa
#define QP 1024       // padded row stride (256*4)

// Transposed per-batch cost slice, padded: ct[b][t][0..899]=cost, [900..1023]=+INF
__device__ float g_ct[BS][T][QP];

// ---------------------------------------------------------------------------
// Kernel 1: cost matrix (R7 config, measured 84us). 12 warps/block, one q per
// warp, targets staged in smem.
// ---------------------------------------------------------------------------
__global__ void __launch_bounds__(32 * CQB) cost_kernel(
    const float* __restrict__ logits,   // [BS*Q, NC]
    const float* __restrict__ pboxes,   // [BS*Q, 4]  cxcywh
    const int*   __restrict__ tgt_ids,  // [NT]
    const float* __restrict__ tbox,     // [NT, 4]    xyxy
    float* __restrict__ C)              // [BS*Q, NT]
{
    const int b     = blockIdx.x / (Q / CQB);
    const int qbase = (blockIdx.x % (Q / CQB)) * CQB;
    const int tid   = threadIdx.x;
    const int lane  = tid & 31;
    const int w     = tid >> 5;          // 0..11
    const int q     = qbase + w;
    const int bq    = b * Q + q;

    __shared__ float4 s_xy[NT];          // target xyxy
    __shared__ int    s_id[NT];          // target class ids
    __shared__ float  sp[CQB][NC];       // per-warp softmax probs

    // stage targets once per block
    const float4* tb4 = reinterpret_cast<const float4*>(tbox);
    for (int j = tid; j < NT; j += 32 * CQB) {
        s_xy[j] = __ldg(tb4 + j);
        s_id[j] = __ldg(tgt_ids + j);
    }

    // per-warp softmax over 92 logits
    const float* L = logits + (size_t)bq * NC;
    float l0 = (lane      < NC) ? __ldg(L + lane)      : -CUDART_INF_F;
    float l1 = (lane + 32 < NC) ? __ldg(L + lane + 32) : -CUDART_INF_F;
    float l2 = (lane + 64 < NC) ? __ldg(L + lane + 64) : -CUDART_INF_F;

    float m = fmaxf(l0, fmaxf(l1, l2));
    #pragma unroll
    for (int o = 16; o; o >>= 1) m = fmaxf(m, __shfl_xor_sync(0xffffffffu, m, o));

    float e0 = (lane      < NC) ? expf(l0 - m) : 0.f;
    float e1 = (lane + 32 < NC) ? expf(l1 - m) : 0.f;
    float e2 = (lane + 64 < NC) ? expf(l2 - m) : 0.f;
    float s = e0 + e1 + e2;
    #pragma unroll
    for (int o = 16; o; o >>= 1) s += __shfl_xor_sync(0xffffffffu, s, o);
    const float inv_s = 1.0f / s;

    if (lane      < NC) sp[w][lane]      = e0 * inv_s;
    if (lane + 32 < NC) sp[w][lane + 32] = e1 * inv_s;
    if (lane + 64 < NC) sp[w][lane + 64] = e2 * inv_s;
    __syncthreads();

    const float cx = pboxes[bq * 4 + 0];
    const float cy = pboxes[bq * 4 + 1];
    const float wd = pboxes[bq * 4 + 2];
    const float ht = pboxes[bq * 4 + 3];
    const float px0 = cx - wd * 0.5f, py0 = cy - ht * 0.5f;
    const float px1 = cx + wd * 0.5f, py1 = cy + ht * 0.5f;
    const float area_a = (px1 - px0) * (py1 - py0);

    float* Crow = C + (size_t)bq * NT;

    for (int j = lane; j < NT; j += 32) {
        const float prob = sp[w][s_id[j]];

        const float4 tb = s_xy[j];
        const float tx0 = tb.x, ty0 = tb.y, tx1 = tb.z, ty1 = tb.w;

        const float tcx = (tx0 + tx1) * 0.5f, tcy = (ty0 + ty1) * 0.5f;
        const float tw  = tx1 - tx0,          th  = ty1 - ty0;

        const float cb = fabsf(cx - tcx) + fabsf(cy - tcy) + fabsf(wd - tw) + fabsf(ht - th);

        const float area_b = tw * th;
        const float ltx = fmaxf(px0, tx0), lty = fmaxf(py0, ty0);
        const float rbx = fminf(px1, tx1), rby = fminf(py1, ty1);
        const float iw = fmaxf(rbx - ltx, 0.f), ih = fmaxf(rby - lty, 0.f);
        const float inter = iw * ih;
        const float uni = area_a + area_b - inter;
        const float iou = inter / uni;
        const float lcx = fminf(px0, tx0), lcy = fminf(py0, ty0);
        const float rcx = fmaxf(px1, tx1), rcy = fmaxf(py1, ty1);
        const float cw = fmaxf(rcx - lcx, 0.f), ch = fmaxf(rcy - lcy, 0.f);
        const float ac = cw * ch;
        const float giou = iou - (ac - uni) / ac;

        float cost = 5.0f * cb + (-prob);
        cost = cost + 2.0f * (-giou);

        Crow[j] = cost;
    }
}

// ---------------------------------------------------------------------------
// Kernel 2: smem-tiled transpose C -> g_ct (own-batch slice) + INF padding.
// ---------------------------------------------------------------------------
__global__ void __launch_bounds__(256) transpose_kernel(const float* __restrict__ C)
{
    const int b  = blockIdx.y;
    const int q0 = blockIdx.x * 32;      // 32 tiles cover q in [0,1024)
    const int tx = threadIdx.x;          // 32
    const int ty = threadIdx.y;          // 8

    __shared__ float tile[32][33];

    #pragma unroll
    for (int t0 = 0; t0 < T; t0 += 32) {
        for (int r = ty; r < 32; r += 8) {
            const int q = q0 + r;
            const int t = t0 + tx;
            float v = 0.f;
            if (q < Q && t < T)
                v = __ldg(C + (size_t)(b * Q + q) * NT + b * T + t);
            tile[r][tx] = v;
        }
        __syncthreads();
        for (int r = ty; r < 32; r += 8) {
            const int t = t0 + r;
            if (t < T) {
                const int q = q0 + tx;
                g_ct[b][t][q] = (q < Q) ? tile[tx][r] : CUDART_INF_F;
            }
        }
        __syncthreads();
    }
}

// ---------------------------------------------------------------------------
// Kernel 3: JV LSA with greedy initialization, 256 threads per batch.
// Phase 0: parallel row mins -> duals u, greedy assignment (~94/100 rows).
// Phase 1: shortest augmenting path only for the ~6 collided rows.
// ---------------------------------------------------------------------------
__device__ __forceinline__ void amin_combine(float& v, int& i, float v2, int i2) {
    if (v2 < v || (v2 == v && i2 < i)) { v = v2; i = i2; }
}

__global__ void __launch_bounds__(LTH) lsa_kernel(
    float* __restrict__ rows_out,   // [BS*T]
    float* __restrict__ cols_out)   // [BS*T]
{
    const int b    = blockIdx.x;
    const int tid  = threadIdx.x;
    const int lane = tid & 31;
    const int wid  = tid >> 5;

    __shared__ float u[T + 1];
    __shared__ int   p[QP + 1];
    __shared__ int   sway[QP + 1];
    __shared__ int   ans[T];
    __shared__ int   gcol[T];        // argmin column (1-based) per row
    __shared__ int   frees[T];
    __shared__ int   nfree;
    __shared__ unsigned long long red[2][8];

    for (int k = tid; k <= QP; k += LTH) p[k] = 0;

    float    v[LNK];
    unsigned minm[LNK];
    float    val[LNK];
    #pragma unroll
    for (int k = 0; k < LNK; ++k) v[k] = 0.f;

    const float* base = &g_ct[b][0][0];

    // ---- Phase 0: row mins (one warp per row, rows strided by 8) ----------
    for (int r = wid; r < T; r += 8) {
        const float* crow = base + (size_t)r * QP;
        float bv = CUDART_INF_F;
        int   bi = 0x7FFFFFF0;
        #pragma unroll
        for (int k = 0; k < QP / 32; ++k) {
            const float c = __ldg(crow + lane + 32 * k);
            if (c < bv) { bv = c; bi = lane + 32 * k; }
        }
        #pragma unroll
        for (int o = 16; o; o >>= 1) {
            const float v2 = __shfl_xor_sync(0xffffffffu, bv, o);
            const int   i2 = __shfl_xor_sync(0xffffffffu, bi, o);
            amin_combine(bv, bi, v2, i2);
        }
        if (lane == 0) { u[r + 1] = bv; gcol[r] = bi + 1; }
    }
    __syncthreads();

    // ---- Phase 0b: greedy assignment (serial, trivial) ---------------------
    if (tid == 0) {
        int nf = 0;
        for (int i = 1; i <= T; ++i) {
            const int j = gcol[i - 1];
            if (p[j] == 0) p[j] = i;
            else           frees[nf++] = i;
        }
        nfree = nf;
    }
    __syncthreads();

    const int nf = nfree;
    int itpar = 0;

    // ---- Phase 1: augmenting path for each free row ------------------------
    for (int fi = 0; fi < nf; ++fi) {
        const int i = frees[fi];

        #pragma unroll
        for (int k = 0; k < LNK; ++k) minm[k] = 0xFFFFFFFFu;
        unsigned usedmask = 0;
        if (tid == 0) p[0] = i;

        int   j0   = 0;
        float u_i0 = u[i];
        float D    = 0.f;

        // prefetch root row
        {
            const float* crow = base + (size_t)(i - 1) * QP;
            #pragma unroll
            for (int k = 0; k < LNK; ++k) val[k] = __ldg(crow + tid + LTH * k);
        }

        while (true) {
            // mark j0 used (at most one (thread,k) matches)
            {
                const int d = j0 - 1 - tid;
                if (d >= 0 && (d & (LTH - 1)) == 0) usedmask |= 1u << (d >> 8);
            }

            const float adj = u_i0 - D;
            unsigned wmin = 0xFFFFFFFFu;
            unsigned mk[LNK];
            #pragma unroll
            for (int k = 0; k < LNK; ++k) {
                const int jc = 1 + tid + LTH * k;
                const float curf = (val[k] - adj) - v[k];
                const unsigned cu = __float_as_uint(curf);
                const unsigned cm = (cu & 0x80000000u) ? ~cu : (cu | 0x80000000u);
                const bool isused = (usedmask >> k) & 1u;
                if (!isused && cm < minm[k]) { minm[k] = cm; sway[jc] = j0; }
                mk[k] = isused ? 0xFFFFFFFFu : minm[k];
                wmin = umin(wmin, mk[k]);
            }
            const unsigned wbest = __reduce_min_sync(0xffffffffu, wmin);

            unsigned idxc = 0x7FFFFFFFu;
            #pragma unroll
            for (int k = 0; k < LNK; ++k) {
                const int jc = 1 + tid + LTH * k;
                if (mk[k] == wbest) idxc = umin(idxc, (unsigned)jc);
            }
            const unsigned widx = __reduce_min_sync(0xffffffffu, idxc);

            if (lane == 0)
                red[itpar][wid] = ((unsigned long long)wbest << 32) | widx;
            __syncthreads();                                   // the ONE barrier

            unsigned long long bk = red[itpar][0];
            #pragma unroll
            for (int ww = 1; ww < 8; ++ww) {
                const unsigned long long c2 = red[itpar][ww];
                if (c2 < bk) bk = c2;
            }
            itpar ^= 1;

            const unsigned bm = (unsigned)(bk >> 32);
            const int      j1 = (int)(unsigned)bk;

            const int i0n = p[j1];
            if (i0n) {
                const float* nrow = base + (size_t)(i0n - 1) * QP;
                #pragma unroll
                for (int k = 0; k < LNK; ++k) val[k] = __ldg(nrow + tid + LTH * k);
            }

            const unsigned ub = (bm & 0x80000000u) ? (bm ^ 0x80000000u) : ~bm;
            const float delta_raw = __uint_as_float(ub);
            const float delta = delta_raw - D;
            D = delta_raw;

            // sparse dual updates (rows of used columns are distinct -> race-free)
            unsigned mm = usedmask;
            while (mm) {
                const int k = __ffs(mm) - 1; mm &= mm - 1;
                const int jc = 1 + tid + LTH * k;
                u[p[jc]] += delta;
                v[k] -= delta;
            }
            if (tid == 0) u[i] += delta;     // virtual column 0 (p[0] = i)

            j0 = j1;
            if (!i0n) break;
            u_i0 = u[i0n];
        }

        __syncthreads();   // sway/u settled before augment
        if (tid == 0) {
            int j0a = j0;
            while (j0a) {
                const int j1a = sway[j0a];
                p[j0a] = p[j1a];
                j0a = j1a;
            }
        }
        __syncthreads();   // p settled before next free row
    }

    // extract: ans[t] = pred column assigned to target t
    for (int jc = 1 + tid; jc <= Q; jc += LTH) {
        const int r = p[jc];
        if (r > 0) ans[r - 1] = jc - 1;
    }
    __syncthreads();

    // rows = sorted pred indices, cols = targets ordered by their pred index
    if (tid < T) {
        const int a = ans[tid];
        int rank = 0;
        #pragma unroll 4
        for (int tt = 0; tt < T; ++tt) rank += (ans[tt] < a);
        rows_out[b * T + rank] = (float)a;
        cols_out[b * T + rank] = (float)tid;
    }
}

// ---------------------------------------------------------------------------
extern "C" void kernel_launch(void* const* d_in, const int* in_sizes, int n_in,
                              void* d_out, int out_size) {
    const float* logits = (const float*)d_in[0];
    const float* pboxes = (const float*)d_in[1];
    const int*   ids    = (const int*)d_in[2];
    const float* tbox   = (const float*)d_in[3];
    float* out = (float*)d_out;

    const long long CN = (long long)BS * Q * NT;   // 23,040,000

    cost_kernel<<<BS * (Q / CQB), 32 * CQB>>>(logits, pboxes, ids, tbox, out);

    dim3 tgrid(32, BS);
    dim3 tblk(32, 8);
    transpose_kernel<<<tgrid, tblk>>>(out);

    if ((long long)out_size >= CN + 2LL * BS * T) {
        lsa_kernel<<<BS, LTH>>>(out + CN, out + CN + (long long)BS * T);
    }
}